// round 4
// baseline (speedup 1.0000x reference)
#include <cuda_runtime.h>
#include <cuda_bf16.h>
#include <math.h>
#include <stdint.h>

// Problem dims
#define BB 4
#define NN 1024
#define LL 1024
#define CC 1024
#define HH 16
#define DD 64
#define BH (BB*HH)          // 64
#define SCALE 0.125f        // D^-0.5
#define NEGV (-65504.0f)

// ---------------- scratch (device globals; no allocations allowed) ----------
__device__ float g_Q[BB*HH*NN*DD];   // (B,H,N,D) 16MB
__device__ float g_K[BB*HH*LL*DD];   // (B,H,L,D) 16MB
__device__ float g_V[BB*HH*LL*DD];   // (B,H,L,D) 16MB
__device__ float g_O[BB*NN*CC];      // (B,N,C)   16MB
__device__ int   g_maskflag;         // 1 => mask stored as 1-byte elems, 0 => 4-byte

// ---------------- mask element-width detection ------------------------------
__global__ void detect_mask_kernel(const unsigned char* __restrict__ m) {
    __shared__ int s;
    if (threadIdx.x == 0) s = 0;
    __syncthreads();
    int found = 0;
    for (int j = threadIdx.x; j < 16384; j += 256)
        if (m[4*j + 1]) found = 1;
    if (found) atomicOr(&s, 1);
    __syncthreads();
    if (threadIdx.x == 0) g_maskflag = s;
}

// ---------------- fp32 -> (hi,lo) bf16x2 conversion --------------------------
__device__ __forceinline__ void cvt8(float4 x, float4 y, float s, uint4& h, uint4& l) {
    float a[8] = {x.x*s, x.y*s, x.z*s, x.w*s, y.x*s, y.y*s, y.z*s, y.w*s};
    unsigned int hh[4], ll[4];
#pragma unroll
    for (int i = 0; i < 4; i++) {
        __nv_bfloat16 h0 = __float2bfloat16(a[2*i]);
        __nv_bfloat16 h1 = __float2bfloat16(a[2*i+1]);
        float r0 = a[2*i]   - __bfloat162float(h0);
        float r1 = a[2*i+1] - __bfloat162float(h1);
        __nv_bfloat16 l0 = __float2bfloat16(r0);
        __nv_bfloat16 l1 = __float2bfloat16(r1);
        hh[i] = (unsigned)__bfloat16_as_ushort(h0) | ((unsigned)__bfloat16_as_ushort(h1) << 16);
        ll[i] = (unsigned)__bfloat16_as_ushort(l0) | ((unsigned)__bfloat16_as_ushort(l1) << 16);
    }
    h = make_uint4(hh[0], hh[1], hh[2], hh[3]);
    l = make_uint4(ll[0], ll[1], ll[2], ll[3]);
}

// ---------------- mma.sync wrapper ------------------------------------------
__device__ __forceinline__ void mma16816(float* c, uint32_t a0, uint32_t a1,
                                         uint32_t a2, uint32_t a3,
                                         uint32_t b0, uint32_t b1) {
    asm volatile(
        "mma.sync.aligned.m16n8k16.row.col.f32.bf16.bf16.f32 "
        "{%0,%1,%2,%3}, {%4,%5,%6,%7}, {%8,%9}, {%0,%1,%2,%3};"
        : "+f"(c[0]), "+f"(c[1]), "+f"(c[2]), "+f"(c[3])
        : "r"(a0), "r"(a1), "r"(a2), "r"(a3), "r"(b0), "r"(b1));
}

// ---------------- epilogue functors (per float2 at (m, n..n+1)) -------------
struct EpiQ {
    __device__ void apply2(int z, int m, int n, float v0, float v1) const {
        int b = m >> 10, nr = m & 1023, h = n >> 6, d = n & 63;
        *(float2*)&g_Q[(((b << 4) + h) * NN + nr) * DD + d] = make_float2(v0, v1);
    }
};
struct EpiKV {
    __device__ void apply2(int z, int m, int n, float v0, float v1) const {
        int b = m >> 10, lr = m & 1023;
        if (n < CC) {
            int h = n >> 6, d = n & 63;
            *(float2*)&g_K[(((b << 4) + h) * LL + lr) * DD + d] = make_float2(v0, v1);
        } else {
            int c = n - CC, h = c >> 6, d = c & 63;
            *(float2*)&g_V[(((b << 4) + h) * LL + lr) * DD + d] = make_float2(v0, v1);
        }
    }
};
struct EpiProj {
    float* out; const float* pb;
    __device__ void apply2(int z, int m, int n, float v0, float v1) const {
        float2 bb = *(const float2*)&pb[n];
        *(float2*)&out[(long)m * CC + n] = make_float2(v0 + bb.x, v1 + bb.y);
    }
};
struct EpiAttn {
    const float* bias; const unsigned char* mask; float* attn;
    __device__ void apply2(int z, int m, int n, float v0, float v1) const {
        long rowb = ((long)z * NN + m) * LL + n;
        long rowm = ((long)(z >> 4) * NN + m) * LL + n;
        if (g_maskflag) {
            if (mask[rowm])     v0 = NEGV;
            if (mask[rowm + 1]) v1 = NEGV;
        } else {
            const unsigned int* m32 = (const unsigned int*)mask;
            if (m32[rowm])     v0 = NEGV;
            if (m32[rowm + 1]) v1 = NEGV;
        }
        float2 bb = *(const float2*)&bias[rowb];
        *(float2*)&attn[rowb] = make_float2(v0 + bb.x, v1 + bb.y);
    }
};

// =================== mma.sync GEMM: C = A @ B^T (bf16 hi/lo split) ==========
// A: M x K row-major fp32 (ld=lda), B: N x K row-major fp32 (ld=ldb).
// 128x128 CTA tile, BK=32, 256 threads (8 warps, each 64x32 warp tile).
// asel: 0 = use A ptr, 1 = g_Q, 2 = g_O. B == nullptr => g_K.
// Smem rows padded to 40 halves (20 words) -> conflict-free fragment LDS.
#define SROW 40

template <class Epi>
__global__ void __launch_bounds__(256, 1)
mma_gemm_kernel(const float* A, const float* Bm, int K, int lda, int ldb,
                long sAz, long sBz, float ascale, int asel, Epi epi) {
    __shared__ __align__(16) __nv_bfloat16 sAh[128 * SROW];
    __shared__ __align__(16) __nv_bfloat16 sAl[128 * SROW];
    __shared__ __align__(16) __nv_bfloat16 sBh[128 * SROW];
    __shared__ __align__(16) __nv_bfloat16 sBl[128 * SROW];

    const float* Aeff = A;
    if (!Aeff) Aeff = (asel == 1) ? g_Q : g_O;
    const float* Beff = Bm ? Bm : g_K;
    int z = blockIdx.z;
    Aeff += (long)z * sAz;
    Beff += (long)z * sBz;

    int tid = threadIdx.x, lane = tid & 31, warp = tid >> 5;
    int m0 = blockIdx.y * 128, n0 = blockIdx.x * 128;
    int wm = (warp >> 2) * 64, wn = (warp & 3) * 32;

    // global-load geometry: each thread loads 16 floats of one row half
    int lr = tid >> 1, lh = tid & 1;
    const float* ap = &Aeff[(long)(m0 + lr) * lda + lh * 16];
    const float* bp = &Beff[(long)(n0 + lr) * ldb + lh * 16];

    float acc[4][4][4];
#pragma unroll
    for (int i = 0; i < 4; i++)
#pragma unroll
        for (int j = 0; j < 4; j++)
#pragma unroll
            for (int q = 0; q < 4; q++) acc[i][j][q] = 0.f;

    float4 pa[4], pb[4];
#pragma unroll
    for (int j = 0; j < 4; j++) {
        pa[j] = *(const float4*)(ap + j * 4);
        pb[j] = *(const float4*)(bp + j * 4);
    }

    const int nch = K >> 5;
    const uint32_t soff = (uint32_t)lr * (SROW / 2) + (uint32_t)lh * 8;  // in words

    for (int c = 0; c < nch; c++) {
        // convert + store chunk c
        {
            uint4 h0, l0, h1, l1;
            cvt8(pa[0], pa[1], ascale, h0, l0);
            cvt8(pa[2], pa[3], ascale, h1, l1);
            ((uint4*)((uint32_t*)sAh + soff))[0] = h0;
            ((uint4*)((uint32_t*)sAh + soff + 4))[0] = h1;
            ((uint4*)((uint32_t*)sAl + soff))[0] = l0;
            ((uint4*)((uint32_t*)sAl + soff + 4))[0] = l1;
            cvt8(pb[0], pb[1], 1.0f, h0, l0);
            cvt8(pb[2], pb[3], 1.0f, h1, l1);
            ((uint4*)((uint32_t*)sBh + soff))[0] = h0;
            ((uint4*)((uint32_t*)sBh + soff + 4))[0] = h1;
            ((uint4*)((uint32_t*)sBl + soff))[0] = l0;
            ((uint4*)((uint32_t*)sBl + soff + 4))[0] = l1;
        }
        __syncthreads();

        // prefetch chunk c+1 (overlaps with MMA below)
        if (c + 1 < nch) {
            ap += 32; bp += 32;
#pragma unroll
            for (int j = 0; j < 4; j++) {
                pa[j] = *(const float4*)(ap + j * 4);
                pb[j] = *(const float4*)(bp + j * 4);
            }
        }

        // 3 passes: Ah*Bh, Ah*Bl, Al*Bh
#pragma unroll
        for (int p = 0; p < 3; p++) {
            const uint32_t* Aw = (const uint32_t*)((p == 2) ? sAl : sAh);
            const uint32_t* Bw = (const uint32_t*)((p == 1) ? sBl : sBh);
#pragma unroll
            for (int s = 0; s < 2; s++) {
                int cw = s * 8 + (lane & 3);
                uint32_t b0[4], b1[4];
#pragma unroll
                for (int nf = 0; nf < 4; nf++) {
                    int rn = wn + nf * 8 + (lane >> 2);
                    b0[nf] = Bw[rn * (SROW / 2) + cw];
                    b1[nf] = Bw[rn * (SROW / 2) + cw + 4];
                }
#pragma unroll
                for (int mf = 0; mf < 4; mf++) {
                    int r0 = wm + mf * 16 + (lane >> 2);
                    uint32_t a0 = Aw[r0 * (SROW / 2) + cw];
                    uint32_t a1 = Aw[(r0 + 8) * (SROW / 2) + cw];
                    uint32_t a2 = Aw[r0 * (SROW / 2) + cw + 4];
                    uint32_t a3 = Aw[(r0 + 8) * (SROW / 2) + cw + 4];
#pragma unroll
                    for (int nf = 0; nf < 4; nf++)
                        mma16816(acc[mf][nf], a0, a1, a2, a3, b0[nf], b1[nf]);
                }
            }
        }
        __syncthreads();
    }

    // epilogue straight from fragments
#pragma unroll
    for (int mf = 0; mf < 4; mf++) {
        int r = m0 + wm + mf * 16 + (lane >> 2);
#pragma unroll
        for (int nf = 0; nf < 4; nf++) {
            int n = n0 + wn + nf * 8 + (lane & 3) * 2;
            epi.apply2(z, r,     n, acc[mf][nf][0], acc[mf][nf][1]);
            epi.apply2(z, r + 8, n, acc[mf][nf][2], acc[mf][nf][3]);
        }
    }
}

// ---------------- fused softmax (over L) + P@V, writes O in (B,N,C) --------
__global__ void __launch_bounds__(256)
softmax_pv_kernel(const float* __restrict__ attn) {
    __shared__ float Ps[64][65];
    __shared__ float Vs[64][64];
    __shared__ float rmax[64], rinv[64];

    int bh = blockIdx.y;
    int r0 = blockIdx.x * 64;
    const float* S = attn + ((long)bh * NN + r0) * LL;

    int tid = threadIdx.x;
    int lane = tid & 31, warp = tid >> 5;

    for (int rr = 0; rr < 8; rr++) {
        int r = warp * 8 + rr;
        const float* srow = S + (long)r * LL;
        float m = -3.4e38f, s = 0.f;
        for (int i = lane; i < LL; i += 32) {
            float x = srow[i];
            float nm = fmaxf(m, x);
            s = s * __expf(m - nm) + __expf(x - nm);
            m = nm;
        }
#pragma unroll
        for (int off = 16; off; off >>= 1) {
            float om = __shfl_down_sync(0xffffffffu, m, off);
            float os = __shfl_down_sync(0xffffffffu, s, off);
            float nm = fmaxf(m, om);
            s = s * __expf(m - nm) + os * __expf(om - nm);
            m = nm;
        }
        if (lane == 0) { rmax[r] = m; rinv[r] = 1.0f / s; }
    }
    __syncthreads();

    float acc[4][4];
#pragma unroll
    for (int i = 0; i < 4; i++)
#pragma unroll
        for (int j = 0; j < 4; j++) acc[i][j] = 0.f;

    int tx = tid & 15, ty = tid >> 4;
    for (int lc = 0; lc < LL; lc += 64) {
#pragma unroll
        for (int i = 0; i < 16; i++) {
            int idx = tid + 256 * i;
            int r = idx >> 6, l = idx & 63;
            float x = S[(long)r * LL + lc + l];
            Ps[r][l] = __expf(x - rmax[r]) * rinv[r];
        }
        const float* Vp = g_V + ((long)bh * LL + lc) * DD;
#pragma unroll
        for (int i = 0; i < 4; i++) {
            int idx = tid + 256 * i;
            int vr = idx >> 4, vq = idx & 15;
            *(float4*)&Vs[vr][vq * 4] = *(const float4*)&Vp[(long)vr * DD + vq * 4];
        }
        __syncthreads();
#pragma unroll
        for (int kk = 0; kk < 64; kk++) {
            float4 bv = *(float4*)&Vs[kk][tx * 4];
            float bb[4] = {bv.x, bv.y, bv.z, bv.w};
            float a[4];
#pragma unroll
            for (int i = 0; i < 4; i++) a[i] = Ps[ty * 4 + i][kk];
#pragma unroll
            for (int i = 0; i < 4; i++)
#pragma unroll
                for (int j = 0; j < 4; j++) acc[i][j] += a[i] * bb[j];
        }
        __syncthreads();
    }

    int b = bh >> 4, h = bh & 15;
#pragma unroll
    for (int i = 0; i < 4; i++) {
        int r = r0 + ty * 4 + i;
        float4 v = make_float4(acc[i][0], acc[i][1], acc[i][2], acc[i][3]);
        *(float4*)&g_O[((long)b * NN + r) * CC + h * DD + tx * 4] = v;
    }
}

// ---------------- launch --------------------------------------------------
extern "C" void kernel_launch(void* const* d_in, const int* in_sizes, int n_in,
                              void* d_out, int out_size) {
    const float* query  = (const float*)d_in[0];
    const float* memory = (const float*)d_in[1];
    const float* bias   = (const float*)d_in[2];
    const unsigned char* mask = (const unsigned char*)d_in[3];
    const float* q_w    = (const float*)d_in[4];
    const float* kv_w   = (const float*)d_in[5];
    const float* proj_w = (const float*)d_in[6];
    const float* proj_b = (const float*)d_in[7];

    float* x_out    = (float*)d_out;
    float* attn_out = x_out + (long)BB * NN * CC;   // x first, then attn_wo_softmax

    (void)in_sizes; (void)n_in; (void)out_size;

    detect_mask_kernel<<<1, 256>>>(mask);

    // Q = query @ q_w^T -> g_Q (B,H,N,D)
    mma_gemm_kernel<EpiQ><<<dim3(CC/128, (BB*NN)/128, 1), 256>>>(
        query, q_w, CC, CC, CC, 0, 0, 1.0f, 0, EpiQ{});
    // KV = memory @ kv_w^T -> g_K, g_V
    mma_gemm_kernel<EpiKV><<<dim3((2*CC)/128, (BB*LL)/128, 1), 256>>>(
        memory, kv_w, CC, CC, CC, 0, 0, 1.0f, 0, EpiKV{});
    // S = (scale*Q) @ K^T, + mask + bias -> attn_wo_softmax
    mma_gemm_kernel<EpiAttn><<<dim3(LL/128, NN/128, BH), 256>>>(
        nullptr, nullptr, DD, DD, DD, (long)NN*DD, (long)LL*DD, SCALE, 1,
        EpiAttn{bias, mask, attn_out});
    // softmax + P@V -> g_O (B,N,C)
    softmax_pv_kernel<<<dim3(NN/64, BH), 256>>>(attn_out);
    // x = O @ proj_w^T + b
    mma_gemm_kernel<EpiProj><<<dim3(CC/128, (BB*NN)/128, 1), 256>>>(
        nullptr, proj_w, CC, CC, CC, 0, 0, 1.0f, 2, EpiProj{x_out, proj_b});
}

// round 5
// speedup vs baseline: 1.5751x; 1.5751x over previous
#include <cuda_runtime.h>
#include <cuda_bf16.h>
#include <math.h>
#include <stdint.h>

// Problem dims
#define BB 4
#define NN 1024
#define LL 1024
#define CC 1024
#define HH 16
#define DD 64
#define BH (BB*HH)          // 64
#define SCALE 0.125f        // D^-0.5
#define NEGV (-65504.0f)

// ---------------- scratch (device globals; no allocations allowed) ----------
__device__ float g_Q[BB*HH*NN*DD];   // (B,H,N,D) 16MB
__device__ float g_K[BB*HH*LL*DD];   // (B,H,L,D) 16MB
__device__ float g_V[BB*HH*LL*DD];   // (B,H,L,D) 16MB
__device__ float g_O[BB*NN*CC];      // (B,N,C)   16MB
__device__ int   g_maskflag;         // 1 => mask stored as 1-byte elems, 0 => 4-byte

// ---------------- mask element-width detection ------------------------------
__global__ void detect_mask_kernel(const unsigned char* __restrict__ m) {
    __shared__ int s;
    if (threadIdx.x == 0) s = 0;
    __syncthreads();
    int found = 0;
    for (int j = threadIdx.x; j < 16384; j += 256)
        if (m[4*j + 1]) found = 1;
    if (found) atomicOr(&s, 1);
    __syncthreads();
    if (threadIdx.x == 0) g_maskflag = s;
}

// ---------------- fp32 -> (hi,lo) bf16x2 conversion --------------------------
__device__ __forceinline__ void cvt8(float4 x, float4 y, float s, uint4& h, uint4& l) {
    float a[8] = {x.x*s, x.y*s, x.z*s, x.w*s, y.x*s, y.y*s, y.z*s, y.w*s};
    unsigned int hh[4], ll[4];
#pragma unroll
    for (int i = 0; i < 4; i++) {
        __nv_bfloat16 h0 = __float2bfloat16(a[2*i]);
        __nv_bfloat16 h1 = __float2bfloat16(a[2*i+1]);
        float r0 = a[2*i]   - __bfloat162float(h0);
        float r1 = a[2*i+1] - __bfloat162float(h1);
        __nv_bfloat16 l0 = __float2bfloat16(r0);
        __nv_bfloat16 l1 = __float2bfloat16(r1);
        hh[i] = (unsigned)__bfloat16_as_ushort(h0) | ((unsigned)__bfloat16_as_ushort(h1) << 16);
        ll[i] = (unsigned)__bfloat16_as_ushort(l0) | ((unsigned)__bfloat16_as_ushort(l1) << 16);
    }
    h = make_uint4(hh[0], hh[1], hh[2], hh[3]);
    l = make_uint4(ll[0], ll[1], ll[2], ll[3]);
}

// ---------------- mma.sync wrapper ------------------------------------------
__device__ __forceinline__ void mma16816(float* c, uint32_t a0, uint32_t a1,
                                         uint32_t a2, uint32_t a3,
                                         uint32_t b0, uint32_t b1) {
    asm volatile(
        "mma.sync.aligned.m16n8k16.row.col.f32.bf16.bf16.f32 "
        "{%0,%1,%2,%3}, {%4,%5,%6,%7}, {%8,%9}, {%0,%1,%2,%3};"
        : "+f"(c[0]), "+f"(c[1]), "+f"(c[2]), "+f"(c[3])
        : "r"(a0), "r"(a1), "r"(a2), "r"(a3), "r"(b0), "r"(b1));
}

// ---------------- epilogue functors (per float2 at (m, n..n+1)) -------------
struct EpiQ {
    __device__ void apply2(int z, int m, int n, float v0, float v1, int) const {
        int b = m >> 10, nr = m & 1023, h = n >> 6, d = n & 63;
        *(float2*)&g_Q[(((b << 4) + h) * NN + nr) * DD + d] = make_float2(v0, v1);
    }
};
struct EpiKV {
    __device__ void apply2(int z, int m, int n, float v0, float v1, int) const {
        int b = m >> 10, lr = m & 1023;
        if (n < CC) {
            int h = n >> 6, d = n & 63;
            *(float2*)&g_K[(((b << 4) + h) * LL + lr) * DD + d] = make_float2(v0, v1);
        } else {
            int c = n - CC, h = c >> 6, d = c & 63;
            *(float2*)&g_V[(((b << 4) + h) * LL + lr) * DD + d] = make_float2(v0, v1);
        }
    }
};
struct EpiProj {
    float* out; const float* pb;
    __device__ void apply2(int z, int m, int n, float v0, float v1, int) const {
        float2 bb = *(const float2*)&pb[n];
        *(float2*)&out[(long)m * CC + n] = make_float2(v0 + bb.x, v1 + bb.y);
    }
};
struct EpiAttn {
    const float* bias; const unsigned char* mask; float* attn;
    __device__ void apply2(int z, int m, int n, float v0, float v1, int flag) const {
        long rowb = ((long)z * NN + m) * LL + n;
        long rowm = ((long)(z >> 4) * NN + m) * LL + n;
        if (flag) {
            unsigned short mm = *(const unsigned short*)&mask[rowm];
            if (mm & 0x00ff) v0 = NEGV;
            if (mm & 0xff00) v1 = NEGV;
        } else {
            uint2 mm = *(const uint2*)&((const unsigned int*)mask)[rowm];
            if (mm.x) v0 = NEGV;
            if (mm.y) v1 = NEGV;
        }
        float2 bb = *(const float2*)&bias[rowb];
        *(float2*)&attn[rowb] = make_float2(v0 + bb.x, v1 + bb.y);
    }
};

// =================== mma.sync GEMM: C = A @ B^T (bf16 hi/lo split) ==========
// A: M x K row-major fp32 (ld=lda), B: N x K row-major fp32 (ld=ldb).
// 128x128 CTA tile, BK=32, 256 threads (8 warps, each 64x32 warp tile).
// Double-buffered smem; 2 CTAs/SM. asel: 0=A ptr, 1=g_Q, 2=g_O. B==nullptr => g_K.
#define SROW 40
#define ARR  (128 * SROW)                 // halves per array
#define SMEM_BYTES (2 * 4 * ARR * 2)      // 81920

template <class Epi>
__global__ void __launch_bounds__(256, 2)
mma_gemm_kernel(const float* A, const float* Bm, int K, int lda, int ldb,
                long sAz, long sBz, float ascale, int asel, Epi epi) {
    extern __shared__ __nv_bfloat16 sm[];
    // layout: [buf][Ah, Al, Bh, Bl], each ARR halves
    const float* Aeff = A;
    if (!Aeff) Aeff = (asel == 1) ? g_Q : g_O;
    const float* Beff = Bm ? Bm : g_K;
    int z = blockIdx.z;
    Aeff += (long)z * sAz;
    Beff += (long)z * sBz;

    int tid = threadIdx.x, lane = tid & 31, warp = tid >> 5;
    int m0 = blockIdx.y * 128, n0 = blockIdx.x * 128;
    int wm = (warp >> 2) * 64, wn = (warp & 3) * 32;

    int lr = tid >> 1, lh = tid & 1;
    const float* ap = &Aeff[(long)(m0 + lr) * lda + lh * 16];
    const float* bp = &Beff[(long)(n0 + lr) * ldb + lh * 16];

    float acc[4][4][4];
#pragma unroll
    for (int i = 0; i < 4; i++)
#pragma unroll
        for (int j = 0; j < 4; j++)
#pragma unroll
            for (int q = 0; q < 4; q++) acc[i][j][q] = 0.f;

    const int nch = K >> 5;
    const uint32_t soff = (uint32_t)lr * (SROW / 2) + (uint32_t)lh * 8;  // words

    float4 pa[4], pb[4];
#pragma unroll
    for (int j = 0; j < 4; j++) {
        pa[j] = *(const float4*)(ap + j * 4);
        pb[j] = *(const float4*)(bp + j * 4);
    }
    // store chunk 0 into buf 0
    {
        uint32_t* wAh = (uint32_t*)(sm + 0 * ARR);
        uint32_t* wAl = (uint32_t*)(sm + 1 * ARR);
        uint32_t* wBh = (uint32_t*)(sm + 2 * ARR);
        uint32_t* wBl = (uint32_t*)(sm + 3 * ARR);
        uint4 h0, l0, h1, l1;
        cvt8(pa[0], pa[1], ascale, h0, l0);
        cvt8(pa[2], pa[3], ascale, h1, l1);
        *(uint4*)(wAh + soff) = h0; *(uint4*)(wAh + soff + 4) = h1;
        *(uint4*)(wAl + soff) = l0; *(uint4*)(wAl + soff + 4) = l1;
        cvt8(pb[0], pb[1], 1.0f, h0, l0);
        cvt8(pb[2], pb[3], 1.0f, h1, l1);
        *(uint4*)(wBh + soff) = h0; *(uint4*)(wBh + soff + 4) = h1;
        *(uint4*)(wBl + soff) = l0; *(uint4*)(wBl + soff + 4) = l1;
    }
    __syncthreads();

    for (int c = 0; c < nch; c++) {
        int buf = c & 1;
        // issue global loads for chunk c+1 (overlap with MMA below)
        bool more = (c + 1 < nch);
        if (more) {
            ap += 32; bp += 32;
#pragma unroll
            for (int j = 0; j < 4; j++) {
                pa[j] = *(const float4*)(ap + j * 4);
                pb[j] = *(const float4*)(bp + j * 4);
            }
        }

        // MMA on buf: 3 passes (Ah*Bh, Ah*Bl, Al*Bh)
        const __nv_bfloat16* base = sm + buf * 4 * ARR;
#pragma unroll
        for (int p = 0; p < 3; p++) {
            const uint32_t* Aw = (const uint32_t*)(base + ((p == 2) ? 1 : 0) * ARR);
            const uint32_t* Bw = (const uint32_t*)(base + ((p == 1) ? 3 : 2) * ARR);
#pragma unroll
            for (int s = 0; s < 2; s++) {
                int cw = s * 8 + (lane & 3);
                uint32_t b0[4], b1[4];
#pragma unroll
                for (int nf = 0; nf < 4; nf++) {
                    int rn = wn + nf * 8 + (lane >> 2);
                    b0[nf] = Bw[rn * (SROW / 2) + cw];
                    b1[nf] = Bw[rn * (SROW / 2) + cw + 4];
                }
#pragma unroll
                for (int mf = 0; mf < 4; mf++) {
                    int r0 = wm + mf * 16 + (lane >> 2);
                    uint32_t a0 = Aw[r0 * (SROW / 2) + cw];
                    uint32_t a1 = Aw[(r0 + 8) * (SROW / 2) + cw];
                    uint32_t a2 = Aw[r0 * (SROW / 2) + cw + 4];
                    uint32_t a3 = Aw[(r0 + 8) * (SROW / 2) + cw + 4];
#pragma unroll
                    for (int nf = 0; nf < 4; nf++)
                        mma16816(acc[mf][nf], a0, a1, a2, a3, b0[nf], b1[nf]);
                }
            }
        }

        // convert + store chunk c+1 into the other buffer
        if (more) {
            __nv_bfloat16* nb = sm + (buf ^ 1) * 4 * ARR;
            uint32_t* wAh = (uint32_t*)(nb + 0 * ARR);
            uint32_t* wAl = (uint32_t*)(nb + 1 * ARR);
            uint32_t* wBh = (uint32_t*)(nb + 2 * ARR);
            uint32_t* wBl = (uint32_t*)(nb + 3 * ARR);
            uint4 h0, l0, h1, l1;
            cvt8(pa[0], pa[1], ascale, h0, l0);
            cvt8(pa[2], pa[3], ascale, h1, l1);
            *(uint4*)(wAh + soff) = h0; *(uint4*)(wAh + soff + 4) = h1;
            *(uint4*)(wAl + soff) = l0; *(uint4*)(wAl + soff + 4) = l1;
            cvt8(pb[0], pb[1], 1.0f, h0, l0);
            cvt8(pb[2], pb[3], 1.0f, h1, l1);
            *(uint4*)(wBh + soff) = h0; *(uint4*)(wBh + soff + 4) = h1;
            *(uint4*)(wBl + soff) = l0; *(uint4*)(wBl + soff + 4) = l1;
        }
        __syncthreads();
    }

    // epilogue straight from fragments
    int flag = g_maskflag;
#pragma unroll
    for (int mf = 0; mf < 4; mf++) {
        int r = m0 + wm + mf * 16 + (lane >> 2);
#pragma unroll
        for (int nf = 0; nf < 4; nf++) {
            int n = n0 + wn + nf * 8 + (lane & 3) * 2;
            epi.apply2(z, r,     n, acc[mf][nf][0], acc[mf][nf][1], flag);
            epi.apply2(z, r + 8, n, acc[mf][nf][2], acc[mf][nf][3], flag);
        }
    }
}

// ------- single-pass online softmax (over L) + P@V, writes O in (B,N,C) ----
__global__ void __launch_bounds__(256)
softmax_pv_kernel(const float* __restrict__ attn) {
    __shared__ float Ps[64][65];
    __shared__ float Vs[64][64];
    __shared__ float rmul[64], rinv[64];

    int bh = blockIdx.y;
    int r0 = blockIdx.x * 64;
    const float* S = attn + ((long)bh * NN + r0) * LL;
    const float* Vbase = g_V + (long)bh * LL * DD;

    int tid = threadIdx.x;
    int orow = tid >> 2, oj = tid & 3;   // 4 owner lanes per row (same warp)
    int tx = tid & 15, ty = tid >> 4;

    float om = -1e30f, os = 0.f;
    float acc[4][4];
#pragma unroll
    for (int i = 0; i < 4; i++)
#pragma unroll
        for (int j = 0; j < 4; j++) acc[i][j] = 0.f;

    for (int lc = 0; lc < LL; lc += 64) {
        // load S chunk (raw) and V chunk
#pragma unroll
        for (int i = 0; i < 4; i++) {
            int idx = tid + 256 * i;
            int r = idx >> 4, q = idx & 15;
            float4 v = *(const float4*)&S[(long)r * LL + lc + q * 4];
            Ps[r][q*4] = v.x; Ps[r][q*4+1] = v.y; Ps[r][q*4+2] = v.z; Ps[r][q*4+3] = v.w;
        }
#pragma unroll
        for (int i = 0; i < 4; i++) {
            int idx = tid + 256 * i;
            int vr = idx >> 4, vq = idx & 15;
            *(float4*)&Vs[vr][vq * 4] = *(const float4*)&Vbase[(long)(lc + vr) * DD + vq * 4];
        }
        __syncthreads();

        // owner lanes: chunk max & sum, update running (m, s), write rescale f
        {
            float cm = -1e30f;
#pragma unroll
            for (int t = 0; t < 16; t++) cm = fmaxf(cm, Ps[orow][oj * 16 + t]);
            cm = fmaxf(cm, __shfl_xor_sync(0xffffffffu, cm, 1));
            cm = fmaxf(cm, __shfl_xor_sync(0xffffffffu, cm, 2));
            float mn = fmaxf(om, cm);
            float cs = 0.f;
#pragma unroll
            for (int t = 0; t < 16; t++) cs += __expf(Ps[orow][oj * 16 + t] - mn);
            cs += __shfl_xor_sync(0xffffffffu, cs, 1);
            cs += __shfl_xor_sync(0xffffffffu, cs, 2);
            float f = __expf(om - mn);
            os = os * f + cs;
            om = mn;
            if (oj == 0) rmul[orow] = f;
            // convert this row-chunk to P = exp(x - mn)
#pragma unroll
            for (int t = 0; t < 16; t++)
                Ps[orow][oj * 16 + t] = __expf(Ps[orow][oj * 16 + t] - mn);
        }
        __syncthreads();

        // rescale acc and accumulate P @ V for this chunk
        float fr[4];
#pragma unroll
        for (int i = 0; i < 4; i++) fr[i] = rmul[ty * 4 + i];
#pragma unroll
        for (int i = 0; i < 4; i++)
#pragma unroll
            for (int j = 0; j < 4; j++) acc[i][j] *= fr[i];
#pragma unroll
        for (int kk = 0; kk < 64; kk++) {
            float4 bv = *(float4*)&Vs[kk][tx * 4];
            float bb[4] = {bv.x, bv.y, bv.z, bv.w};
            float a[4];
#pragma unroll
            for (int i = 0; i < 4; i++) a[i] = Ps[ty * 4 + i][kk];
#pragma unroll
            for (int i = 0; i < 4; i++)
#pragma unroll
                for (int j = 0; j < 4; j++) acc[i][j] += a[i] * bb[j];
        }
        __syncthreads();
    }

    if (oj == 0) rinv[orow] = 1.0f / os;
    __syncthreads();

    int b = bh >> 4, h = bh & 15;
#pragma unroll
    for (int i = 0; i < 4; i++) {
        int r = r0 + ty * 4 + i;
        float rv = rinv[ty * 4 + i];
        float4 v = make_float4(acc[i][0] * rv, acc[i][1] * rv,
                               acc[i][2] * rv, acc[i][3] * rv);
        *(float4*)&g_O[((long)b * NN + r) * CC + h * DD + tx * 4] = v;
    }
}

// ---------------- launch --------------------------------------------------
extern "C" void kernel_launch(void* const* d_in, const int* in_sizes, int n_in,
                              void* d_out, int out_size) {
    const float* query  = (const float*)d_in[0];
    const float* memory = (const float*)d_in[1];
    const float* bias   = (const float*)d_in[2];
    const unsigned char* mask = (const unsigned char*)d_in[3];
    const float* q_w    = (const float*)d_in[4];
    const float* kv_w   = (const float*)d_in[5];
    const float* proj_w = (const float*)d_in[6];
    const float* proj_b = (const float*)d_in[7];

    float* x_out    = (float*)d_out;
    float* attn_out = x_out + (long)BB * NN * CC;   // x first, then attn_wo_softmax

    (void)in_sizes; (void)n_in; (void)out_size;

    cudaFuncSetAttribute(mma_gemm_kernel<EpiQ>,    cudaFuncAttributeMaxDynamicSharedMemorySize, SMEM_BYTES);
    cudaFuncSetAttribute(mma_gemm_kernel<EpiKV>,   cudaFuncAttributeMaxDynamicSharedMemorySize, SMEM_BYTES);
    cudaFuncSetAttribute(mma_gemm_kernel<EpiAttn>, cudaFuncAttributeMaxDynamicSharedMemorySize, SMEM_BYTES);
    cudaFuncSetAttribute(mma_gemm_kernel<EpiProj>, cudaFuncAttributeMaxDynamicSharedMemorySize, SMEM_BYTES);

    detect_mask_kernel<<<1, 256>>>(mask);

    // Q = query @ q_w^T -> g_Q (B,H,N,D)
    mma_gemm_kernel<EpiQ><<<dim3(CC/128, (BB*NN)/128, 1), 256, SMEM_BYTES>>>(
        query, q_w, CC, CC, CC, 0, 0, 1.0f, 0, EpiQ{});
    // KV = memory @ kv_w^T -> g_K, g_V
    mma_gemm_kernel<EpiKV><<<dim3((2*CC)/128, (BB*LL)/128, 1), 256, SMEM_BYTES>>>(
        memory, kv_w, CC, CC, CC, 0, 0, 1.0f, 0, EpiKV{});
    // S = (scale*Q) @ K^T, + mask + bias -> attn_wo_softmax
    mma_gemm_kernel<EpiAttn><<<dim3(LL/128, NN/128, BH), 256, SMEM_BYTES>>>(
        nullptr, nullptr, DD, DD, DD, (long)NN*DD, (long)LL*DD, SCALE, 1,
        EpiAttn{bias, mask, attn_out});
    // online softmax + P@V -> g_O (B,N,C)
    softmax_pv_kernel<<<dim3(NN/64, BH), 256>>>(attn_out);
    // x = O @ proj_w^T + b
    mma_gemm_kernel<EpiProj><<<dim3(CC/128, (BB*NN)/128, 1), 256, SMEM_BYTES>>>(
        nullptr, proj_w, CC, CC, CC, 0, 0, 1.0f, 2, EpiProj{x_out, proj_b});
}

// round 6
// speedup vs baseline: 1.9018x; 1.2074x over previous
#include <cuda_runtime.h>
#include <cuda_bf16.h>
#include <math.h>
#include <stdint.h>

// Problem dims
#define BB 4
#define NN 1024
#define LL 1024
#define CC 1024
#define HH 16
#define DD 64
#define BH (BB*HH)          // 64
#define SCALE 0.125f        // D^-0.5
#define NEGV (-65504.0f)

// ---------------- scratch (device globals; no allocations allowed) ----------
__device__ float g_Q[BB*HH*NN*DD];   // (B,H,N,D) 16MB
__device__ float g_K[BB*HH*LL*DD];   // (B,H,L,D) 16MB
__device__ float g_V[BB*HH*LL*DD];   // (B,H,L,D) 16MB
__device__ float g_O[BB*NN*CC];      // (B,N,C)   16MB
__device__ int   g_maskflag;         // 1 => mask stored as 1-byte elems, 0 => 4-byte

// ---------------- mask element-width detection ------------------------------
__global__ void detect_mask_kernel(const unsigned char* __restrict__ m) {
    __shared__ int s;
    if (threadIdx.x == 0) s = 0;
    __syncthreads();
    int found = 0;
    for (int j = threadIdx.x; j < 16384; j += 256)
        if (m[4*j + 1]) found = 1;
    if (found) atomicOr(&s, 1);
    __syncthreads();
    if (threadIdx.x == 0) g_maskflag = s;
}

// ---------------- fp32 -> (hi,lo) bf16x2 conversion --------------------------
__device__ __forceinline__ void cvt8(float4 x, float4 y, float s, uint4& h, uint4& l) {
    float a[8] = {x.x*s, x.y*s, x.z*s, x.w*s, y.x*s, y.y*s, y.z*s, y.w*s};
    unsigned int hh[4], ll[4];
#pragma unroll
    for (int i = 0; i < 4; i++) {
        __nv_bfloat16 h0 = __float2bfloat16(a[2*i]);
        __nv_bfloat16 h1 = __float2bfloat16(a[2*i+1]);
        float r0 = a[2*i]   - __bfloat162float(h0);
        float r1 = a[2*i+1] - __bfloat162float(h1);
        __nv_bfloat16 l0 = __float2bfloat16(r0);
        __nv_bfloat16 l1 = __float2bfloat16(r1);
        hh[i] = (unsigned)__bfloat16_as_ushort(h0) | ((unsigned)__bfloat16_as_ushort(h1) << 16);
        ll[i] = (unsigned)__bfloat16_as_ushort(l0) | ((unsigned)__bfloat16_as_ushort(l1) << 16);
    }
    h = make_uint4(hh[0], hh[1], hh[2], hh[3]);
    l = make_uint4(ll[0], ll[1], ll[2], ll[3]);
}

__device__ __forceinline__ uint32_t pack2bf(float x0, float x1, float& r0, float& r1) {
    __nv_bfloat16 h0 = __float2bfloat16(x0);
    __nv_bfloat16 h1 = __float2bfloat16(x1);
    r0 = x0 - __bfloat162float(h0);
    r1 = x1 - __bfloat162float(h1);
    return (unsigned)__bfloat16_as_ushort(h0) | ((unsigned)__bfloat16_as_ushort(h1) << 16);
}
__device__ __forceinline__ uint32_t pack2bf_only(float x0, float x1) {
    __nv_bfloat16 h0 = __float2bfloat16(x0);
    __nv_bfloat16 h1 = __float2bfloat16(x1);
    return (unsigned)__bfloat16_as_ushort(h0) | ((unsigned)__bfloat16_as_ushort(h1) << 16);
}

// ---------------- mma.sync wrapper ------------------------------------------
__device__ __forceinline__ void mma16816(float* c, uint32_t a0, uint32_t a1,
                                         uint32_t a2, uint32_t a3,
                                         uint32_t b0, uint32_t b1) {
    asm volatile(
        "mma.sync.aligned.m16n8k16.row.col.f32.bf16.bf16.f32 "
        "{%0,%1,%2,%3}, {%4,%5,%6,%7}, {%8,%9}, {%0,%1,%2,%3};"
        : "+f"(c[0]), "+f"(c[1]), "+f"(c[2]), "+f"(c[3])
        : "r"(a0), "r"(a1), "r"(a2), "r"(a3), "r"(b0), "r"(b1));
}

// ---------------- epilogue functors (per float2 at (m, n..n+1)) -------------
struct EpiQ {
    __device__ void apply2(int z, int m, int n, float v0, float v1, int) const {
        int b = m >> 10, nr = m & 1023, h = n >> 6, d = n & 63;
        *(float2*)&g_Q[(((b << 4) + h) * NN + nr) * DD + d] = make_float2(v0, v1);
    }
};
struct EpiKV {
    __device__ void apply2(int z, int m, int n, float v0, float v1, int) const {
        int b = m >> 10, lr = m & 1023;
        if (n < CC) {
            int h = n >> 6, d = n & 63;
            *(float2*)&g_K[(((b << 4) + h) * LL + lr) * DD + d] = make_float2(v0, v1);
        } else {
            int c = n - CC, h = c >> 6, d = c & 63;
            *(float2*)&g_V[(((b << 4) + h) * LL + lr) * DD + d] = make_float2(v0, v1);
        }
    }
};
struct EpiProj {
    float* out; const float* pb;
    __device__ void apply2(int z, int m, int n, float v0, float v1, int) const {
        float2 bb = *(const float2*)&pb[n];
        *(float2*)&out[(long)m * CC + n] = make_float2(v0 + bb.x, v1 + bb.y);
    }
};

// =================== mma.sync GEMM: C = A @ B^T (bf16 hi/lo split) ==========
#define SROW 40
#define ARR  (128 * SROW)                 // halves per array
#define SMEM_BYTES (2 * 4 * ARR * 2)      // 81920

template <class Epi>
__global__ void __launch_bounds__(256, 2)
mma_gemm_kernel(const float* A, const float* Bm, int K, int lda, int ldb,
                long sAz, long sBz, float ascale, int asel, Epi epi) {
    extern __shared__ __nv_bfloat16 sm[];
    const float* Aeff = A;
    if (!Aeff) Aeff = (asel == 1) ? g_Q : g_O;
    const float* Beff = Bm ? Bm : g_K;
    int z = blockIdx.z;
    Aeff += (long)z * sAz;
    Beff += (long)z * sBz;

    int tid = threadIdx.x, lane = tid & 31, warp = tid >> 5;
    int m0 = blockIdx.y * 128, n0 = blockIdx.x * 128;
    int wm = (warp >> 2) * 64, wn = (warp & 3) * 32;

    int lr = tid >> 1, lh = tid & 1;
    const float* ap = &Aeff[(long)(m0 + lr) * lda + lh * 16];
    const float* bp = &Beff[(long)(n0 + lr) * ldb + lh * 16];

    float acc[4][4][4];
#pragma unroll
    for (int i = 0; i < 4; i++)
#pragma unroll
        for (int j = 0; j < 4; j++)
#pragma unroll
            for (int q = 0; q < 4; q++) acc[i][j][q] = 0.f;

    const int nch = K >> 5;
    const uint32_t soff = (uint32_t)lr * (SROW / 2) + (uint32_t)lh * 8;  // words

    float4 pa[4], pb[4];
#pragma unroll
    for (int j = 0; j < 4; j++) {
        pa[j] = *(const float4*)(ap + j * 4);
        pb[j] = *(const float4*)(bp + j * 4);
    }
    {
        uint32_t* wAh = (uint32_t*)(sm + 0 * ARR);
        uint32_t* wAl = (uint32_t*)(sm + 1 * ARR);
        uint32_t* wBh = (uint32_t*)(sm + 2 * ARR);
        uint32_t* wBl = (uint32_t*)(sm + 3 * ARR);
        uint4 h0, l0, h1, l1;
        cvt8(pa[0], pa[1], ascale, h0, l0);
        cvt8(pa[2], pa[3], ascale, h1, l1);
        *(uint4*)(wAh + soff) = h0; *(uint4*)(wAh + soff + 4) = h1;
        *(uint4*)(wAl + soff) = l0; *(uint4*)(wAl + soff + 4) = l1;
        cvt8(pb[0], pb[1], 1.0f, h0, l0);
        cvt8(pb[2], pb[3], 1.0f, h1, l1);
        *(uint4*)(wBh + soff) = h0; *(uint4*)(wBh + soff + 4) = h1;
        *(uint4*)(wBl + soff) = l0; *(uint4*)(wBl + soff + 4) = l1;
    }
    __syncthreads();

    for (int c = 0; c < nch; c++) {
        int buf = c & 1;
        bool more = (c + 1 < nch);
        if (more) {
            ap += 32; bp += 32;
#pragma unroll
            for (int j = 0; j < 4; j++) {
                pa[j] = *(const float4*)(ap + j * 4);
                pb[j] = *(const float4*)(bp + j * 4);
            }
        }

        const __nv_bfloat16* base = sm + buf * 4 * ARR;
#pragma unroll
        for (int p = 0; p < 3; p++) {
            const uint32_t* Aw = (const uint32_t*)(base + ((p == 2) ? 1 : 0) * ARR);
            const uint32_t* Bw = (const uint32_t*)(base + ((p == 1) ? 3 : 2) * ARR);
#pragma unroll
            for (int s = 0; s < 2; s++) {
                int cw = s * 8 + (lane & 3);
                uint32_t b0[4], b1[4];
#pragma unroll
                for (int nf = 0; nf < 4; nf++) {
                    int rn = wn + nf * 8 + (lane >> 2);
                    b0[nf] = Bw[rn * (SROW / 2) + cw];
                    b1[nf] = Bw[rn * (SROW / 2) + cw + 4];
                }
#pragma unroll
                for (int mf = 0; mf < 4; mf++) {
                    int r0 = wm + mf * 16 + (lane >> 2);
                    uint32_t a0 = Aw[r0 * (SROW / 2) + cw];
                    uint32_t a1 = Aw[(r0 + 8) * (SROW / 2) + cw];
                    uint32_t a2 = Aw[r0 * (SROW / 2) + cw + 4];
                    uint32_t a3 = Aw[(r0 + 8) * (SROW / 2) + cw + 4];
#pragma unroll
                    for (int nf = 0; nf < 4; nf++)
                        mma16816(acc[mf][nf], a0, a1, a2, a3, b0[nf], b1[nf]);
                }
            }
        }

        if (more) {
            __nv_bfloat16* nb = sm + (buf ^ 1) * 4 * ARR;
            uint32_t* wAh = (uint32_t*)(nb + 0 * ARR);
            uint32_t* wAl = (uint32_t*)(nb + 1 * ARR);
            uint32_t* wBh = (uint32_t*)(nb + 2 * ARR);
            uint32_t* wBl = (uint32_t*)(nb + 3 * ARR);
            uint4 h0, l0, h1, l1;
            cvt8(pa[0], pa[1], ascale, h0, l0);
            cvt8(pa[2], pa[3], ascale, h1, l1);
            *(uint4*)(wAh + soff) = h0; *(uint4*)(wAh + soff + 4) = h1;
            *(uint4*)(wAl + soff) = l0; *(uint4*)(wAl + soff + 4) = l1;
            cvt8(pb[0], pb[1], 1.0f, h0, l0);
            cvt8(pb[2], pb[3], 1.0f, h1, l1);
            *(uint4*)(wBh + soff) = h0; *(uint4*)(wBh + soff + 4) = h1;
            *(uint4*)(wBl + soff) = l0; *(uint4*)(wBl + soff + 4) = l1;
        }
        __syncthreads();
    }

    int flag = g_maskflag;
#pragma unroll
    for (int mf = 0; mf < 4; mf++) {
        int r = m0 + wm + mf * 16 + (lane >> 2);
#pragma unroll
        for (int nf = 0; nf < 4; nf++) {
            int n = n0 + wn + nf * 8 + (lane & 3) * 2;
            epi.apply2(z, r,     n, acc[mf][nf][0], acc[mf][nf][1], flag);
            epi.apply2(z, r + 8, n, acc[mf][nf][2], acc[mf][nf][3], flag);
        }
    }
}

// ============ fused flash attention: S=(scale Q)K^T +mask+bias -> attn_out,
// ============ online softmax, O = P@V (mma, 3-pass hi/lo) -> g_O ============
// CTA: (bh, 128 rows). 8 warps, each 16 rows x 128 cols of S.
// smem halves layout: Qh[128*72] Ql[128*72] Kh[128*72] Kl[128*72]
//                     Vth[64*136] Vtl[64*136]  (Vt: word-packed l-pairs, stride 68 words)
#define FA_SMEM_HALVES (4*9216 + 2*8704)
#define FA_SMEM_BYTES  (FA_SMEM_HALVES*2)    // 108544

__global__ void __launch_bounds__(256, 1)
flash_attn_kernel(const float* __restrict__ bias,
                  const unsigned char* __restrict__ mask8,
                  float* __restrict__ attn) {
    extern __shared__ __nv_bfloat16 fsm[];
    uint32_t* Qh = (uint32_t*)(fsm);
    uint32_t* Ql = (uint32_t*)(fsm + 9216);
    uint32_t* Kh = (uint32_t*)(fsm + 18432);
    uint32_t* Kl = (uint32_t*)(fsm + 27648);
    uint32_t* Vh = (uint32_t*)(fsm + 36864);
    uint32_t* Vl = (uint32_t*)(fsm + 45568);

    int bh = blockIdx.y, m0 = blockIdx.x * 128;
    int b = bh >> 4, h = bh & 15;
    int tid = threadIdx.x, lane = tid & 31, w = tid >> 5;
    int g = lane >> 2, t = lane & 3;

    const float* Qp = g_Q + (long)bh * NN * DD;
    const float* Kp = g_K + (long)bh * LL * DD;
    const float* Vp = g_V + (long)bh * LL * DD;

    int lr = tid >> 1, lh = tid & 1;
    const uint32_t soq = (uint32_t)(lr * 36 + lh * 16);   // words

    // ---- Q producer (scaled), persists whole kernel ----
    {
        const float* src = Qp + (long)(m0 + lr) * DD + lh * 32;
        float4 v0 = *(const float4*)(src), v1 = *(const float4*)(src + 4);
        float4 v2 = *(const float4*)(src + 8), v3 = *(const float4*)(src + 12);
        float4 v4 = *(const float4*)(src + 16), v5 = *(const float4*)(src + 20);
        float4 v6 = *(const float4*)(src + 24), v7 = *(const float4*)(src + 28);
        uint4 H, L;
        cvt8(v0, v1, SCALE, H, L); *(uint4*)(Qh + soq) = H;      *(uint4*)(Ql + soq) = L;
        cvt8(v2, v3, SCALE, H, L); *(uint4*)(Qh + soq + 4) = H;  *(uint4*)(Ql + soq + 4) = L;
        cvt8(v4, v5, SCALE, H, L); *(uint4*)(Qh + soq + 8) = H;  *(uint4*)(Ql + soq + 8) = L;
        cvt8(v6, v7, SCALE, H, L); *(uint4*)(Qh + soq + 12) = H; *(uint4*)(Ql + soq + 12) = L;
    }

    float om0 = -1e30f, os0 = 0.f, om1 = -1e30f, os1 = 0.f;
    float acco[8][4];
#pragma unroll
    for (int i = 0; i < 8; i++)
#pragma unroll
        for (int q = 0; q < 4; q++) acco[i][q] = 0.f;

    const int arow = 16 * w + g;
    const int flag = g_maskflag;

    __syncthreads();

    for (int lc = 0; lc < 8; lc++) {
        // ---- K producer ----
        {
            const float* src = Kp + (long)(lc * 128 + lr) * DD + lh * 32;
            float4 v0 = *(const float4*)(src), v1 = *(const float4*)(src + 4);
            float4 v2 = *(const float4*)(src + 8), v3 = *(const float4*)(src + 12);
            float4 v4 = *(const float4*)(src + 16), v5 = *(const float4*)(src + 20);
            float4 v6 = *(const float4*)(src + 24), v7 = *(const float4*)(src + 28);
            uint4 H, L;
            cvt8(v0, v1, 1.f, H, L); *(uint4*)(Kh + soq) = H;      *(uint4*)(Kl + soq) = L;
            cvt8(v2, v3, 1.f, H, L); *(uint4*)(Kh + soq + 4) = H;  *(uint4*)(Kl + soq + 4) = L;
            cvt8(v4, v5, 1.f, H, L); *(uint4*)(Kh + soq + 8) = H;  *(uint4*)(Kl + soq + 8) = L;
            cvt8(v6, v7, 1.f, H, L); *(uint4*)(Kh + soq + 12) = H; *(uint4*)(Kl + soq + 12) = L;
        }
        // ---- V producer: transposed pair-packed ----
#pragma unroll
        for (int it = 0; it < 4; it++) {
            int T = tid + 256 * it;
            int dg = T & 15, lp = T >> 4;                 // d group (4 wide), l-pair 0..63
            const float* vp = Vp + (long)(lc * 128 + 2 * lp) * DD + dg * 4;
            float4 a = *(const float4*)vp;
            float4 c = *(const float4*)(vp + DD);
            float av[4] = {a.x, a.y, a.z, a.w};
            float cv[4] = {c.x, c.y, c.z, c.w};
#pragma unroll
            for (int j = 0; j < 4; j++) {
                int d = dg * 4 + j;
                float r0, r1;
                uint32_t hi = pack2bf(av[j], cv[j], r0, r1);
                Vh[d * 68 + lp] = hi;
                Vl[d * 68 + lp] = pack2bf_only(r0, r1);
            }
        }
        __syncthreads();

        // ---- S = Q @ K^T (3-pass hi/lo) ----
        float sacc[16][4];
#pragma unroll
        for (int i = 0; i < 16; i++)
#pragma unroll
            for (int q = 0; q < 4; q++) sacc[i][q] = 0.f;

#pragma unroll
        for (int ks = 0; ks < 4; ks++) {
            uint32_t aw = (uint32_t)(arow * 36 + ks * 8 + t);
            uint32_t ah0 = Qh[aw], ah1 = Qh[aw + 8 * 36], ah2 = Qh[aw + 4], ah3 = Qh[aw + 8 * 36 + 4];
            uint32_t al0 = Ql[aw], al1 = Ql[aw + 8 * 36], al2 = Ql[aw + 4], al3 = Ql[aw + 8 * 36 + 4];
#pragma unroll
            for (int nf = 0; nf < 16; nf++) {
                uint32_t kw = (uint32_t)((nf * 8 + g) * 36 + ks * 8 + t);
                uint32_t b0 = Kh[kw], b1 = Kh[kw + 4];
                mma16816(sacc[nf], ah0, ah1, ah2, ah3, b0, b1);
                mma16816(sacc[nf], al0, al1, al2, al3, b0, b1);
            }
#pragma unroll
            for (int nf = 0; nf < 16; nf++) {
                uint32_t kw = (uint32_t)((nf * 8 + g) * 36 + ks * 8 + t);
                uint32_t b0 = Kl[kw], b1 = Kl[kw + 4];
                mma16816(sacc[nf], ah0, ah1, ah2, ah3, b0, b1);
            }
        }

        // ---- mask + bias, write attn_wo_softmax ----
        int r0g = m0 + arow;
        long rb0 = ((long)bh * NN + r0g) * LL + lc * 128;
        long rb1 = rb0 + 8 * LL;
        long rm0 = ((long)b * NN + r0g) * LL + lc * 128;
        long rm1 = rm0 + 8 * LL;
#pragma unroll
        for (int nf = 0; nf < 16; nf++) {
            int col = nf * 8 + 2 * t;
            float v0 = sacc[nf][0], v1 = sacc[nf][1];
            float v2 = sacc[nf][2], v3 = sacc[nf][3];
            if (flag) {
                unsigned short mA = *(const unsigned short*)&mask8[rm0 + col];
                unsigned short mB = *(const unsigned short*)&mask8[rm1 + col];
                if (mA & 0x00ff) v0 = NEGV;
                if (mA & 0xff00) v1 = NEGV;
                if (mB & 0x00ff) v2 = NEGV;
                if (mB & 0xff00) v3 = NEGV;
            } else {
                const unsigned int* m32 = (const unsigned int*)mask8;
                uint2 mA = *(const uint2*)&m32[rm0 + col];
                uint2 mB = *(const uint2*)&m32[rm1 + col];
                if (mA.x) v0 = NEGV;
                if (mA.y) v1 = NEGV;
                if (mB.x) v2 = NEGV;
                if (mB.y) v3 = NEGV;
            }
            float2 bb0 = *(const float2*)&bias[rb0 + col];
            float2 bb1 = *(const float2*)&bias[rb1 + col];
            v0 += bb0.x; v1 += bb0.y; v2 += bb1.x; v3 += bb1.y;
            *(float2*)&attn[rb0 + col] = make_float2(v0, v1);
            *(float2*)&attn[rb1 + col] = make_float2(v2, v3);
            sacc[nf][0] = v0; sacc[nf][1] = v1; sacc[nf][2] = v2; sacc[nf][3] = v3;
        }

        // ---- online softmax stats ----
        float cm0 = -1e30f, cm1 = -1e30f;
#pragma unroll
        for (int nf = 0; nf < 16; nf++) {
            cm0 = fmaxf(cm0, fmaxf(sacc[nf][0], sacc[nf][1]));
            cm1 = fmaxf(cm1, fmaxf(sacc[nf][2], sacc[nf][3]));
        }
        cm0 = fmaxf(cm0, __shfl_xor_sync(0xffffffffu, cm0, 1));
        cm0 = fmaxf(cm0, __shfl_xor_sync(0xffffffffu, cm0, 2));
        cm1 = fmaxf(cm1, __shfl_xor_sync(0xffffffffu, cm1, 1));
        cm1 = fmaxf(cm1, __shfl_xor_sync(0xffffffffu, cm1, 2));
        float mn0 = fmaxf(om0, cm0), mn1 = fmaxf(om1, cm1);

        uint32_t pph0[16], pph1[16], ppl0[16], ppl1[16];
        float cs0 = 0.f, cs1 = 0.f;
#pragma unroll
        for (int nf = 0; nf < 16; nf++) {
            float p0 = __expf(sacc[nf][0] - mn0);
            float p1 = __expf(sacc[nf][1] - mn0);
            float p2 = __expf(sacc[nf][2] - mn1);
            float p3 = __expf(sacc[nf][3] - mn1);
            cs0 += p0 + p1; cs1 += p2 + p3;
            float r0, r1;
            pph0[nf] = pack2bf(p0, p1, r0, r1);
            ppl0[nf] = pack2bf_only(r0, r1);
            pph1[nf] = pack2bf(p2, p3, r0, r1);
            ppl1[nf] = pack2bf_only(r0, r1);
        }
        cs0 += __shfl_xor_sync(0xffffffffu, cs0, 1);
        cs0 += __shfl_xor_sync(0xffffffffu, cs0, 2);
        cs1 += __shfl_xor_sync(0xffffffffu, cs1, 1);
        cs1 += __shfl_xor_sync(0xffffffffu, cs1, 2);
        float f0 = __expf(om0 - mn0), f1 = __expf(om1 - mn1);
        os0 = os0 * f0 + cs0; os1 = os1 * f1 + cs1;
        om0 = mn0; om1 = mn1;

#pragma unroll
        for (int nb = 0; nb < 8; nb++) {
            acco[nb][0] *= f0; acco[nb][1] *= f0;
            acco[nb][2] *= f1; acco[nb][3] *= f1;
        }

        // ---- O += P @ V (3-pass hi/lo), V^T frags from smem ----
#pragma unroll
        for (int ks = 0; ks < 8; ks++) {
            uint32_t pa0 = pph0[2*ks], pa1 = pph1[2*ks], pa2 = pph0[2*ks+1], pa3 = pph1[2*ks+1];
            uint32_t qa0 = ppl0[2*ks], qa1 = ppl1[2*ks], qa2 = ppl0[2*ks+1], qa3 = ppl1[2*ks+1];
#pragma unroll
            for (int nb = 0; nb < 8; nb++) {
                uint32_t vw = (uint32_t)((nb * 8 + g) * 68 + ks * 8 + t);
                uint32_t b0 = Vh[vw], b1 = Vh[vw + 4];
                mma16816(acco[nb], pa0, pa1, pa2, pa3, b0, b1);
                mma16816(acco[nb], qa0, qa1, qa2, qa3, b0, b1);
            }
#pragma unroll
            for (int nb = 0; nb < 8; nb++) {
                uint32_t vw = (uint32_t)((nb * 8 + g) * 68 + ks * 8 + t);
                uint32_t b0 = Vl[vw], b1 = Vl[vw + 4];
                mma16816(acco[nb], pa0, pa1, pa2, pa3, b0, b1);
            }
        }
        __syncthreads();
    }

    // ---- O epilogue ----
    float rv0 = 1.0f / os0, rv1 = 1.0f / os1;
    int r0g = m0 + arow;
    long ob0 = ((long)b * NN + r0g) * CC + h * 64;
    long ob1 = ((long)b * NN + r0g + 8) * CC + h * 64;
#pragma unroll
    for (int nb = 0; nb < 8; nb++) {
        int d = nb * 8 + 2 * t;
        *(float2*)&g_O[ob0 + d] = make_float2(acco[nb][0] * rv0, acco[nb][1] * rv0);
        *(float2*)&g_O[ob1 + d] = make_float2(acco[nb][2] * rv1, acco[nb][3] * rv1);
    }
}

// ---------------- launch --------------------------------------------------
extern "C" void kernel_launch(void* const* d_in, const int* in_sizes, int n_in,
                              void* d_out, int out_size) {
    const float* query  = (const float*)d_in[0];
    const float* memory = (const float*)d_in[1];
    const float* bias   = (const float*)d_in[2];
    const unsigned char* mask = (const unsigned char*)d_in[3];
    const float* q_w    = (const float*)d_in[4];
    const float* kv_w   = (const float*)d_in[5];
    const float* proj_w = (const float*)d_in[6];
    const float* proj_b = (const float*)d_in[7];

    float* x_out    = (float*)d_out;
    float* attn_out = x_out + (long)BB * NN * CC;   // x first, then attn_wo_softmax

    (void)in_sizes; (void)n_in; (void)out_size;

    cudaFuncSetAttribute(mma_gemm_kernel<EpiQ>,    cudaFuncAttributeMaxDynamicSharedMemorySize, SMEM_BYTES);
    cudaFuncSetAttribute(mma_gemm_kernel<EpiKV>,   cudaFuncAttributeMaxDynamicSharedMemorySize, SMEM_BYTES);
    cudaFuncSetAttribute(mma_gemm_kernel<EpiProj>, cudaFuncAttributeMaxDynamicSharedMemorySize, SMEM_BYTES);
    cudaFuncSetAttribute(flash_attn_kernel,        cudaFuncAttributeMaxDynamicSharedMemorySize, FA_SMEM_BYTES);

    detect_mask_kernel<<<1, 256>>>(mask);

    // Q = query @ q_w^T -> g_Q (B,H,N,D)
    mma_gemm_kernel<EpiQ><<<dim3(CC/128, (BB*NN)/128, 1), 256, SMEM_BYTES>>>(
        query, q_w, CC, CC, CC, 0, 0, 1.0f, 0, EpiQ{});
    // KV = memory @ kv_w^T -> g_K, g_V
    mma_gemm_kernel<EpiKV><<<dim3((2*CC)/128, (BB*LL)/128, 1), 256, SMEM_BYTES>>>(
        memory, kv_w, CC, CC, CC, 0, 0, 1.0f, 0, EpiKV{});
    // fused: S (+mask+bias) -> attn_out, online softmax, O = P@V -> g_O
    flash_attn_kernel<<<dim3(NN/128, BH), 256, FA_SMEM_BYTES>>>(bias, mask, attn_out);
    // x = O @ proj_w^T + b
    mma_gemm_kernel<EpiProj><<<dim3(CC/128, (BB*NN)/128, 1), 256, SMEM_BYTES>>>(
        nullptr, proj_w, CC, CC, CC, 0, 0, 1.0f, 2, EpiProj{x_out, proj_b});
}

// round 7
// speedup vs baseline: 2.5750x; 1.3539x over previous
#include <cuda_runtime.h>
#include <cuda_bf16.h>
#include <math.h>
#include <stdint.h>

// Problem dims
#define BB 4
#define NN 1024
#define LL 1024
#define CC 1024
#define HH 16
#define DD 64
#define BH (BB*HH)          // 64
#define SCALE 0.125f        // D^-0.5
#define NEGV (-65504.0f)

// ---------------- scratch (device globals; no allocations allowed) ----------
__device__ float g_Q[BB*HH*NN*DD];   // (B,H,N,D) 16MB
__device__ float g_K[BB*HH*LL*DD];   // (B,H,L,D) 16MB
__device__ float g_V[BB*HH*LL*DD];   // (B,H,L,D) 16MB
__device__ float g_O[BB*NN*CC];      // (B,N,C)   16MB
__device__ int   g_maskflag;         // 1 => mask stored as 1-byte elems, 0 => 4-byte

// converted bf16 hi/lo operand buffers (reused serially between GEMMs)
__device__ __nv_bfloat16 g_cAh[BB*NN*CC];    // activations hi (4M)
__device__ __nv_bfloat16 g_cAl[BB*NN*CC];    // activations lo
__device__ __nv_bfloat16 g_cBh[2*CC*CC];     // weights hi (2M max, kv_w)
__device__ __nv_bfloat16 g_cBl[2*CC*CC];     // weights lo

// ============================ helpers ========================================
__device__ __forceinline__ uint32_t smem_u32(const void* p) {
    uint32_t a;
    asm("{ .reg .u64 t; cvta.to.shared.u64 t, %1; cvt.u32.u64 %0, t; }" : "=r"(a) : "l"(p));
    return a;
}

__device__ __forceinline__ void cvt8(float4 x, float4 y, float s, uint4& h, uint4& l) {
    float a[8] = {x.x*s, x.y*s, x.z*s, x.w*s, y.x*s, y.y*s, y.z*s, y.w*s};
    unsigned int hh[4], ll[4];
#pragma unroll
    for (int i = 0; i < 4; i++) {
        __nv_bfloat16 h0 = __float2bfloat16(a[2*i]);
        __nv_bfloat16 h1 = __float2bfloat16(a[2*i+1]);
        float r0 = a[2*i]   - __bfloat162float(h0);
        float r1 = a[2*i+1] - __bfloat162float(h1);
        __nv_bfloat16 l0 = __float2bfloat16(r0);
        __nv_bfloat16 l1 = __float2bfloat16(r1);
        hh[i] = (unsigned)__bfloat16_as_ushort(h0) | ((unsigned)__bfloat16_as_ushort(h1) << 16);
        ll[i] = (unsigned)__bfloat16_as_ushort(l0) | ((unsigned)__bfloat16_as_ushort(l1) << 16);
    }
    h = make_uint4(hh[0], hh[1], hh[2], hh[3]);
    l = make_uint4(ll[0], ll[1], ll[2], ll[3]);
}

__device__ __forceinline__ uint32_t pack2bf(float x0, float x1, float& r0, float& r1) {
    __nv_bfloat16 h0 = __float2bfloat16(x0);
    __nv_bfloat16 h1 = __float2bfloat16(x1);
    r0 = x0 - __bfloat162float(h0);
    r1 = x1 - __bfloat162float(h1);
    return (unsigned)__bfloat16_as_ushort(h0) | ((unsigned)__bfloat16_as_ushort(h1) << 16);
}
__device__ __forceinline__ uint32_t pack2bf_only(float x0, float x1) {
    __nv_bfloat16 h0 = __float2bfloat16(x0);
    __nv_bfloat16 h1 = __float2bfloat16(x1);
    return (unsigned)__bfloat16_as_ushort(h0) | ((unsigned)__bfloat16_as_ushort(h1) << 16);
}

__device__ __forceinline__ void mma16816(float* c, uint32_t a0, uint32_t a1,
                                         uint32_t a2, uint32_t a3,
                                         uint32_t b0, uint32_t b1) {
    asm volatile(
        "mma.sync.aligned.m16n8k16.row.col.f32.bf16.bf16.f32 "
        "{%0,%1,%2,%3}, {%4,%5,%6,%7}, {%8,%9}, {%0,%1,%2,%3};"
        : "+f"(c[0]), "+f"(c[1]), "+f"(c[2]), "+f"(c[3])
        : "r"(a0), "r"(a1), "r"(a2), "r"(a3), "r"(b0), "r"(b1));
}

__device__ __forceinline__ void ldsm4(uint32_t* r, uint32_t addr) {
    asm volatile("ldmatrix.sync.aligned.m8n8.x4.shared.b16 {%0,%1,%2,%3}, [%4];"
        : "=r"(r[0]), "=r"(r[1]), "=r"(r[2]), "=r"(r[3]) : "r"(addr));
}

__device__ __forceinline__ void cp16(uint32_t saddr, const void* g) {
    asm volatile("cp.async.cg.shared.global [%0], [%1], 16;" :: "r"(saddr), "l"(g));
}
#define CP_COMMIT() asm volatile("cp.async.commit_group;" ::: "memory")
#define CP_WAIT2()  asm volatile("cp.async.wait_group 2;" ::: "memory")

// ---------------- mask element-width detection ------------------------------
__global__ void detect_mask_kernel(const unsigned char* __restrict__ m) {
    __shared__ int s;
    if (threadIdx.x == 0) s = 0;
    __syncthreads();
    int found = 0;
    for (int j = threadIdx.x; j < 16384; j += 256)
        if (m[4*j + 1]) found = 1;
    if (found) atomicOr(&s, 1);
    __syncthreads();
    if (threadIdx.x == 0) g_maskflag = s;
}

// ---------------- fp32 -> bf16 hi/lo conversion kernel ----------------------
__global__ void __launch_bounds__(256)
conv_hilo_kernel(const float* __restrict__ x, __nv_bfloat16* __restrict__ oh,
                 __nv_bfloat16* __restrict__ ol, int n8, int asel) {
    const float* src = x;
    if (!src) src = g_O;     // asel: O conversion reads scratch
    int i = blockIdx.x * 256 + threadIdx.x;
    if (i < n8) {
        float4 a = ((const float4*)src)[2*i];
        float4 b = ((const float4*)src)[2*i + 1];
        uint4 h, l;
        cvt8(a, b, 1.0f, h, l);
        ((uint4*)oh)[i] = h;
        ((uint4*)ol)[i] = l;
    }
    (void)asel;
}

// ---------------- epilogue functors (per float2 at (m, n..n+1)) -------------
struct EpiQ {
    __device__ void apply2(int m, int n, float v0, float v1) const {
        int b = m >> 10, nr = m & 1023, h = n >> 6, d = n & 63;
        *(float2*)&g_Q[(((b << 4) + h) * NN + nr) * DD + d] = make_float2(v0, v1);
    }
};
struct EpiKV {
    __device__ void apply2(int m, int n, float v0, float v1) const {
        int b = m >> 10, lr = m & 1023;
        if (n < CC) {
            int h = n >> 6, d = n & 63;
            *(float2*)&g_K[(((b << 4) + h) * LL + lr) * DD + d] = make_float2(v0, v1);
        } else {
            int c = n - CC, h = c >> 6, d = c & 63;
            *(float2*)&g_V[(((b << 4) + h) * LL + lr) * DD + d] = make_float2(v0, v1);
        }
    }
};
struct EpiProj {
    float* out; const float* pb;
    __device__ void apply2(int m, int n, float v0, float v1) const {
        float2 bb = *(const float2*)&pb[n];
        *(float2*)&out[(long)m * CC + n] = make_float2(v0 + bb.x, v1 + bb.y);
    }
};

// ====== pipelined bf16 GEMM: C = A @ B^T, pre-converted hi/lo operands ======
// 128x128 CTA tile, BK=32, 3-stage cp.async, ldmatrix frags, 2 CTA/SM.
// smem stage: Ah[8KB] Al[8KB] Bh[8KB] Bl[8KB] = 32KB; rows 64B, seg^=(row>>1)&3.
#define GS_AH 0
#define GS_AL 8192
#define GS_BH 16384
#define GS_BL 24576
#define GS_STAGE 32768
#define G_SMEM_BYTES (3 * GS_STAGE)   // 98304

template <class Epi>
__global__ void __launch_bounds__(256, 2)
bf16_gemm_kernel(const __nv_bfloat16* __restrict__ Ah_, const __nv_bfloat16* __restrict__ Al_,
                 const __nv_bfloat16* __restrict__ Bh_, const __nv_bfloat16* __restrict__ Bl_,
                 int K, Epi epi) {
    extern __shared__ char smem[];
    uint32_t sbase = smem_u32(smem);
    int tid = threadIdx.x, lane = tid & 31, warp = tid >> 5;
    int m0 = blockIdx.y * 128, n0 = blockIdx.x * 128;
    int wm = (warp >> 2) * 64, wn = (warp & 3) * 32;

    // cp.async geometry: 2 threads per row, 2 x 16B segs each per array
    int row = tid >> 1, hs = tid & 1;
    int sw = (row >> 1) & 3;
    uint32_t off0 = (uint32_t)(row * 64 + (((2*hs)   ^ sw) << 4));
    uint32_t off1 = (uint32_t)(row * 64 + (((2*hs+1) ^ sw) << 4));
    const __nv_bfloat16* gAh = Ah_ + (long)(m0 + row) * K + hs * 16;
    const __nv_bfloat16* gAl = Al_ + (long)(m0 + row) * K + hs * 16;
    const __nv_bfloat16* gBh = Bh_ + (long)(n0 + row) * K + hs * 16;
    const __nv_bfloat16* gBl = Bl_ + (long)(n0 + row) * K + hs * 16;

    float acc[4][4][4];
#pragma unroll
    for (int i = 0; i < 4; i++)
#pragma unroll
        for (int j = 0; j < 4; j++)
#pragma unroll
            for (int q = 0; q < 4; q++) acc[i][j][q] = 0.f;

    const int nch = K >> 5;

    auto issue = [&](int stage, int k0) {
        uint32_t sb = sbase + stage * GS_STAGE;
        cp16(sb + GS_AH + off0, gAh + k0);
        cp16(sb + GS_AH + off1, gAh + k0 + 8);
        cp16(sb + GS_AL + off0, gAl + k0);
        cp16(sb + GS_AL + off1, gAl + k0 + 8);
        cp16(sb + GS_BH + off0, gBh + k0);
        cp16(sb + GS_BH + off1, gBh + k0 + 8);
        cp16(sb + GS_BL + off0, gBl + k0);
        cp16(sb + GS_BL + off1, gBl + k0 + 8);
    };

    // ldmatrix per-lane address components
    // A frags: row_a = wm + mf*16 + (lane&15); kseg = ks*2 + (lane>>4)
    int arow_l = (lane & 15);
    int akse   = (lane >> 4);
    // B frags: row_b = wn + np*16 + ((lane>>4)<<3) + (lane&7); kseg = ks*2 + ((lane>>3)&1)
    int brow_l = ((lane >> 4) << 3) + (lane & 7);
    int bkse   = ((lane >> 3) & 1);

    issue(0, 0);  CP_COMMIT();
    issue(1, 32); CP_COMMIT();

    for (int c = 0; c < nch; c++) {
        if (c + 2 < nch) issue((c + 2) % 3, (c + 2) * 32);
        CP_COMMIT();
        CP_WAIT2();
        __syncthreads();

        uint32_t sb = sbase + (c % 3) * GS_STAGE;
#pragma unroll
        for (int ks = 0; ks < 2; ks++) {
            uint32_t a[4][4], bh[2][4], bl[2][4];
#pragma unroll
            for (int mf = 0; mf < 4; mf++) {
                int r = wm + mf * 16 + arow_l;
                int kg = ks * 2 + akse;
                ldsm4(a[mf], sb + GS_AH + r * 64 + ((kg ^ ((r >> 1) & 3)) << 4));
            }
#pragma unroll
            for (int np = 0; np < 2; np++) {
                int r = wn + np * 16 + brow_l;
                int kg = ks * 2 + bkse;
                uint32_t ro = (uint32_t)(r * 64 + ((kg ^ ((r >> 1) & 3)) << 4));
                ldsm4(bh[np], sb + GS_BH + ro);
                ldsm4(bl[np], sb + GS_BL + ro);
            }
            // Ah*Bh and Ah*Bl
#pragma unroll
            for (int mf = 0; mf < 4; mf++)
#pragma unroll
                for (int nf = 0; nf < 4; nf++) {
                    int np = nf >> 1, o = (nf & 1) * 2;
                    mma16816(acc[mf][nf], a[mf][0], a[mf][1], a[mf][2], a[mf][3],
                             bh[np][o], bh[np][o + 1]);
                }
#pragma unroll
            for (int mf = 0; mf < 4; mf++)
#pragma unroll
                for (int nf = 0; nf < 4; nf++) {
                    int np = nf >> 1, o = (nf & 1) * 2;
                    mma16816(acc[mf][nf], a[mf][0], a[mf][1], a[mf][2], a[mf][3],
                             bl[np][o], bl[np][o + 1]);
                }
            // Al*Bh (reload a with Al)
#pragma unroll
            for (int mf = 0; mf < 4; mf++) {
                int r = wm + mf * 16 + arow_l;
                int kg = ks * 2 + akse;
                ldsm4(a[mf], sb + GS_AL + r * 64 + ((kg ^ ((r >> 1) & 3)) << 4));
            }
#pragma unroll
            for (int mf = 0; mf < 4; mf++)
#pragma unroll
                for (int nf = 0; nf < 4; nf++) {
                    int np = nf >> 1, o = (nf & 1) * 2;
                    mma16816(acc[mf][nf], a[mf][0], a[mf][1], a[mf][2], a[mf][3],
                             bh[np][o], bh[np][o + 1]);
                }
        }
        __syncthreads();
    }

    // epilogue straight from fragments
#pragma unroll
    for (int mf = 0; mf < 4; mf++) {
        int r = m0 + wm + mf * 16 + (lane >> 2);
#pragma unroll
        for (int nf = 0; nf < 4; nf++) {
            int n = n0 + wn + nf * 8 + (lane & 3) * 2;
            epi.apply2(r,     n, acc[mf][nf][0], acc[mf][nf][1]);
            epi.apply2(r + 8, n, acc[mf][nf][2], acc[mf][nf][3]);
        }
    }
}

// ============ fused flash attention (unchanged from R6) =====================
#define FA_SMEM_HALVES (4*9216 + 2*8704)
#define FA_SMEM_BYTES  (FA_SMEM_HALVES*2)    // 108544

__global__ void __launch_bounds__(256, 1)
flash_attn_kernel(const float* __restrict__ bias,
                  const unsigned char* __restrict__ mask8,
                  float* __restrict__ attn) {
    extern __shared__ __nv_bfloat16 fsm[];
    uint32_t* Qh = (uint32_t*)(fsm);
    uint32_t* Ql = (uint32_t*)(fsm + 9216);
    uint32_t* Kh = (uint32_t*)(fsm + 18432);
    uint32_t* Kl = (uint32_t*)(fsm + 27648);
    uint32_t* Vh = (uint32_t*)(fsm + 36864);
    uint32_t* Vl = (uint32_t*)(fsm + 45568);

    int bh = blockIdx.y, m0 = blockIdx.x * 128;
    int b = bh >> 4, h = bh & 15;
    int tid = threadIdx.x, lane = tid & 31, w = tid >> 5;
    int g = lane >> 2, t = lane & 3;

    const float* Qp = g_Q + (long)bh * NN * DD;
    const float* Kp = g_K + (long)bh * LL * DD;
    const float* Vp = g_V + (long)bh * LL * DD;

    int lr = tid >> 1, lh = tid & 1;
    const uint32_t soq = (uint32_t)(lr * 36 + lh * 16);   // words

    {
        const float* src = Qp + (long)(m0 + lr) * DD + lh * 32;
        float4 v0 = *(const float4*)(src), v1 = *(const float4*)(src + 4);
        float4 v2 = *(const float4*)(src + 8), v3 = *(const float4*)(src + 12);
        float4 v4 = *(const float4*)(src + 16), v5 = *(const float4*)(src + 20);
        float4 v6 = *(const float4*)(src + 24), v7 = *(const float4*)(src + 28);
        uint4 H, L;
        cvt8(v0, v1, SCALE, H, L); *(uint4*)(Qh + soq) = H;      *(uint4*)(Ql + soq) = L;
        cvt8(v2, v3, SCALE, H, L); *(uint4*)(Qh + soq + 4) = H;  *(uint4*)(Ql + soq + 4) = L;
        cvt8(v4, v5, SCALE, H, L); *(uint4*)(Qh + soq + 8) = H;  *(uint4*)(Ql + soq + 8) = L;
        cvt8(v6, v7, SCALE, H, L); *(uint4*)(Qh + soq + 12) = H; *(uint4*)(Ql + soq + 12) = L;
    }

    float om0 = -1e30f, os0 = 0.f, om1 = -1e30f, os1 = 0.f;
    float acco[8][4];
#pragma unroll
    for (int i = 0; i < 8; i++)
#pragma unroll
        for (int q = 0; q < 4; q++) acco[i][q] = 0.f;

    const int arow = 16 * w + g;
    const int flag = g_maskflag;

    __syncthreads();

    for (int lc = 0; lc < 8; lc++) {
        {
            const float* src = Kp + (long)(lc * 128 + lr) * DD + lh * 32;
            float4 v0 = *(const float4*)(src), v1 = *(const float4*)(src + 4);
            float4 v2 = *(const float4*)(src + 8), v3 = *(const float4*)(src + 12);
            float4 v4 = *(const float4*)(src + 16), v5 = *(const float4*)(src + 20);
            float4 v6 = *(const float4*)(src + 24), v7 = *(const float4*)(src + 28);
            uint4 H, L;
            cvt8(v0, v1, 1.f, H, L); *(uint4*)(Kh + soq) = H;      *(uint4*)(Kl + soq) = L;
            cvt8(v2, v3, 1.f, H, L); *(uint4*)(Kh + soq + 4) = H;  *(uint4*)(Kl + soq + 4) = L;
            cvt8(v4, v5, 1.f, H, L); *(uint4*)(Kh + soq + 8) = H;  *(uint4*)(Kl + soq + 8) = L;
            cvt8(v6, v7, 1.f, H, L); *(uint4*)(Kh + soq + 12) = H; *(uint4*)(Kl + soq + 12) = L;
        }
#pragma unroll
        for (int it = 0; it < 4; it++) {
            int T = tid + 256 * it;
            int dg = T & 15, lp = T >> 4;
            const float* vp = Vp + (long)(lc * 128 + 2 * lp) * DD + dg * 4;
            float4 a = *(const float4*)vp;
            float4 c = *(const float4*)(vp + DD);
            float av[4] = {a.x, a.y, a.z, a.w};
            float cv[4] = {c.x, c.y, c.z, c.w};
#pragma unroll
            for (int j = 0; j < 4; j++) {
                int d = dg * 4 + j;
                float r0, r1;
                uint32_t hi = pack2bf(av[j], cv[j], r0, r1);
                Vh[d * 68 + lp] = hi;
                Vl[d * 68 + lp] = pack2bf_only(r0, r1);
            }
        }
        __syncthreads();

        float sacc[16][4];
#pragma unroll
        for (int i = 0; i < 16; i++)
#pragma unroll
            for (int q = 0; q < 4; q++) sacc[i][q] = 0.f;

#pragma unroll
        for (int ks = 0; ks < 4; ks++) {
            uint32_t aw = (uint32_t)(arow * 36 + ks * 8 + t);
            uint32_t ah0 = Qh[aw], ah1 = Qh[aw + 8 * 36], ah2 = Qh[aw + 4], ah3 = Qh[aw + 8 * 36 + 4];
            uint32_t al0 = Ql[aw], al1 = Ql[aw + 8 * 36], al2 = Ql[aw + 4], al3 = Ql[aw + 8 * 36 + 4];
#pragma unroll
            for (int nf = 0; nf < 16; nf++) {
                uint32_t kw = (uint32_t)((nf * 8 + g) * 36 + ks * 8 + t);
                uint32_t b0 = Kh[kw], b1 = Kh[kw + 4];
                mma16816(sacc[nf], ah0, ah1, ah2, ah3, b0, b1);
                mma16816(sacc[nf], al0, al1, al2, al3, b0, b1);
            }
#pragma unroll
            for (int nf = 0; nf < 16; nf++) {
                uint32_t kw = (uint32_t)((nf * 8 + g) * 36 + ks * 8 + t);
                uint32_t b0 = Kl[kw], b1 = Kl[kw + 4];
                mma16816(sacc[nf], ah0, ah1, ah2, ah3, b0, b1);
            }
        }

        int r0g = m0 + arow;
        long rb0 = ((long)bh * NN + r0g) * LL + lc * 128;
        long rb1 = rb0 + 8 * LL;
        long rm0 = ((long)b * NN + r0g) * LL + lc * 128;
        long rm1 = rm0 + 8 * LL;
#pragma unroll
        for (int nf = 0; nf < 16; nf++) {
            int col = nf * 8 + 2 * t;
            float v0 = sacc[nf][0], v1 = sacc[nf][1];
            float v2 = sacc[nf][2], v3 = sacc[nf][3];
            if (flag) {
                unsigned short mA = *(const unsigned short*)&mask8[rm0 + col];
                unsigned short mB = *(const unsigned short*)&mask8[rm1 + col];
                if (mA & 0x00ff) v0 = NEGV;
                if (mA & 0xff00) v1 = NEGV;
                if (mB & 0x00ff) v2 = NEGV;
                if (mB & 0xff00) v3 = NEGV;
            } else {
                const unsigned int* m32 = (const unsigned int*)mask8;
                uint2 mA = *(const uint2*)&m32[rm0 + col];
                uint2 mB = *(const uint2*)&m32[rm1 + col];
                if (mA.x) v0 = NEGV;
                if (mA.y) v1 = NEGV;
                if (mB.x) v2 = NEGV;
                if (mB.y) v3 = NEGV;
            }
            float2 bb0 = *(const float2*)&bias[rb0 + col];
            float2 bb1 = *(const float2*)&bias[rb1 + col];
            v0 += bb0.x; v1 += bb0.y; v2 += bb1.x; v3 += bb1.y;
            *(float2*)&attn[rb0 + col] = make_float2(v0, v1);
            *(float2*)&attn[rb1 + col] = make_float2(v2, v3);
            sacc[nf][0] = v0; sacc[nf][1] = v1; sacc[nf][2] = v2; sacc[nf][3] = v3;
        }

        float cm0 = -1e30f, cm1 = -1e30f;
#pragma unroll
        for (int nf = 0; nf < 16; nf++) {
            cm0 = fmaxf(cm0, fmaxf(sacc[nf][0], sacc[nf][1]));
            cm1 = fmaxf(cm1, fmaxf(sacc[nf][2], sacc[nf][3]));
        }
        cm0 = fmaxf(cm0, __shfl_xor_sync(0xffffffffu, cm0, 1));
        cm0 = fmaxf(cm0, __shfl_xor_sync(0xffffffffu, cm0, 2));
        cm1 = fmaxf(cm1, __shfl_xor_sync(0xffffffffu, cm1, 1));
        cm1 = fmaxf(cm1, __shfl_xor_sync(0xffffffffu, cm1, 2));
        float mn0 = fmaxf(om0, cm0), mn1 = fmaxf(om1, cm1);

        uint32_t pph0[16], pph1[16], ppl0[16], ppl1[16];
        float cs0 = 0.f, cs1 = 0.f;
#pragma unroll
        for (int nf = 0; nf < 16; nf++) {
            float p0 = __expf(sacc[nf][0] - mn0);
            float p1 = __expf(sacc[nf][1] - mn0);
            float p2 = __expf(sacc[nf][2] - mn1);
            float p3 = __expf(sacc[nf][3] - mn1);
            cs0 += p0 + p1; cs1 += p2 + p3;
            float r0, r1;
            pph0[nf] = pack2bf(p0, p1, r0, r1);
            ppl0[nf] = pack2bf_only(r0, r1);
            pph1[nf] = pack2bf(p2, p3, r0, r1);
            ppl1[nf] = pack2bf_only(r0, r1);
        }
        cs0 += __shfl_xor_sync(0xffffffffu, cs0, 1);
        cs0 += __shfl_xor_sync(0xffffffffu, cs0, 2);
        cs1 += __shfl_xor_sync(0xffffffffu, cs1, 1);
        cs1 += __shfl_xor_sync(0xffffffffu, cs1, 2);
        float f0 = __expf(om0 - mn0), f1 = __expf(om1 - mn1);
        os0 = os0 * f0 + cs0; os1 = os1 * f1 + cs1;
        om0 = mn0; om1 = mn1;

#pragma unroll
        for (int nb = 0; nb < 8; nb++) {
            acco[nb][0] *= f0; acco[nb][1] *= f0;
            acco[nb][2] *= f1; acco[nb][3] *= f1;
        }

#pragma unroll
        for (int ks = 0; ks < 8; ks++) {
            uint32_t pa0 = pph0[2*ks], pa1 = pph1[2*ks], pa2 = pph0[2*ks+1], pa3 = pph1[2*ks+1];
            uint32_t qa0 = ppl0[2*ks], qa1 = ppl1[2*ks], qa2 = ppl0[2*ks+1], qa3 = ppl1[2*ks+1];
#pragma unroll
            for (int nb = 0; nb < 8; nb++) {
                uint32_t vw = (uint32_t)((nb * 8 + g) * 68 + ks * 8 + t);
                uint32_t b0 = Vh[vw], b1 = Vh[vw + 4];
                mma16816(acco[nb], pa0, pa1, pa2, pa3, b0, b1);
                mma16816(acco[nb], qa0, qa1, qa2, qa3, b0, b1);
            }
#pragma unroll
            for (int nb = 0; nb < 8; nb++) {
                uint32_t vw = (uint32_t)((nb * 8 + g) * 68 + ks * 8 + t);
                uint32_t b0 = Vl[vw], b1 = Vl[vw + 4];
                mma16816(acco[nb], pa0, pa1, pa2, pa3, b0, b1);
            }
        }
        __syncthreads();
    }

    float rv0 = 1.0f / os0, rv1 = 1.0f / os1;
    int r0g = m0 + arow;
    long ob0 = ((long)b * NN + r0g) * CC + h * 64;
    long ob1 = ((long)b * NN + r0g + 8) * CC + h * 64;
#pragma unroll
    for (int nb = 0; nb < 8; nb++) {
        int d = nb * 8 + 2 * t;
        *(float2*)&g_O[ob0 + d] = make_float2(acco[nb][0] * rv0, acco[nb][1] * rv0);
        *(float2*)&g_O[ob1 + d] = make_float2(acco[nb][2] * rv1, acco[nb][3] * rv1);
    }
}

// ---------------- launch --------------------------------------------------
static __nv_bfloat16* dev_ptr_bf(const void* sym) { return nullptr; } // unused

extern "C" void kernel_launch(void* const* d_in, const int* in_sizes, int n_in,
                              void* d_out, int out_size) {
    const float* query  = (const float*)d_in[0];
    const float* memory = (const float*)d_in[1];
    const float* bias   = (const float*)d_in[2];
    const unsigned char* mask = (const unsigned char*)d_in[3];
    const float* q_w    = (const float*)d_in[4];
    const float* kv_w   = (const float*)d_in[5];
    const float* proj_w = (const float*)d_in[6];
    const float* proj_b = (const float*)d_in[7];

    float* x_out    = (float*)d_out;
    float* attn_out = x_out + (long)BB * NN * CC;   // x first, then attn_wo_softmax

    (void)in_sizes; (void)n_in; (void)out_size;

    // resolve device-global buffer addresses (host-side, outside capture-sensitive APIs:
    // cudaGetSymbolAddress is allowed — it does not allocate)
    static __nv_bfloat16 *cAh = nullptr, *cAl = nullptr, *cBh = nullptr, *cBl = nullptr;
    if (!cAh) {
        void* p;
        cudaGetSymbolAddress(&p, g_cAh); cAh = (__nv_bfloat16*)p;
        cudaGetSymbolAddress(&p, g_cAl); cAl = (__nv_bfloat16*)p;
        cudaGetSymbolAddress(&p, g_cBh); cBh = (__nv_bfloat16*)p;
        cudaGetSymbolAddress(&p, g_cBl); cBl = (__nv_bfloat16*)p;
        cudaFuncSetAttribute(bf16_gemm_kernel<EpiQ>,    cudaFuncAttributeMaxDynamicSharedMemorySize, G_SMEM_BYTES);
        cudaFuncSetAttribute(bf16_gemm_kernel<EpiKV>,   cudaFuncAttributeMaxDynamicSharedMemorySize, G_SMEM_BYTES);
        cudaFuncSetAttribute(bf16_gemm_kernel<EpiProj>, cudaFuncAttributeMaxDynamicSharedMemorySize, G_SMEM_BYTES);
        cudaFuncSetAttribute(flash_attn_kernel,         cudaFuncAttributeMaxDynamicSharedMemorySize, FA_SMEM_BYTES);
    }

    detect_mask_kernel<<<1, 256>>>(mask);

    // --- Q projection ---
    conv_hilo_kernel<<<(BB*NN*CC/8 + 255)/256, 256>>>(query, cAh, cAl, BB*NN*CC/8, 0);
    conv_hilo_kernel<<<(CC*CC/8 + 255)/256, 256>>>(q_w, cBh, cBl, CC*CC/8, 0);
    bf16_gemm_kernel<EpiQ><<<dim3(CC/128, (BB*NN)/128), 256, G_SMEM_BYTES>>>(
        cAh, cAl, cBh, cBl, CC, EpiQ{});

    // --- KV projection ---
    conv_hilo_kernel<<<(BB*LL*CC/8 + 255)/256, 256>>>(memory, cAh, cAl, BB*LL*CC/8, 0);
    conv_hilo_kernel<<<(2*CC*CC/8 + 255)/256, 256>>>(kv_w, cBh, cBl, 2*CC*CC/8, 0);
    bf16_gemm_kernel<EpiKV><<<dim3((2*CC)/128, (BB*LL)/128), 256, G_SMEM_BYTES>>>(
        cAh, cAl, cBh, cBl, CC, EpiKV{});

    // --- fused attention: S (+mask+bias) -> attn_out, online softmax, O -> g_O ---
    flash_attn_kernel<<<dim3(NN/128, BH), 256, FA_SMEM_BYTES>>>(bias, mask, attn_out);

    // --- output projection ---
    conv_hilo_kernel<<<(BB*NN*CC/8 + 255)/256, 256>>>(nullptr, cAh, cAl, BB*NN*CC/8, 1);
    conv_hilo_kernel<<<(CC*CC/8 + 255)/256, 256>>>(proj_w, cBh, cBl, CC*CC/8, 0);
    bf16_gemm_kernel<EpiProj><<<dim3(CC/128, (BB*NN)/128), 256, G_SMEM_BYTES>>>(
        cAh, cAl, cBh, cBl, CC, EpiProj{x_out, proj_b});
}